// round 3
// baseline (speedup 1.0000x reference)
#include <cuda_runtime.h>
#include <cuda_bf16.h>
#include <cstdint>

// DifferentiableExtrusion: B=4, N=32 polygons, P=32 edges, V=96 grid.
// out[b,z,y,x] = (z < hv[b]) * max_{n valid} sigmoid(-100 * sdf_n(x,y))
//
// Strategy: one thread per (b, grid point). Per-block shared cache of all
// 1024 edges of that batch with precomputed reciprocals (no divisions in the
// inner loop). min over squared distance, single sqrt per polygon. Crossing
// parity via XOR. Invalid polygons skipped warp-uniformly. z-extrusion fused
// (coalesced stores: each row of 96 is exactly 3 warps).

#define V 96
#define NPOLY 32
#define PEDGE 32
#define NEDGES (NPOLY * PEDGE)   // 1024
#define SHARPNESS 100.0f
#define EPS 1e-8f

__global__ __launch_bounds__(256, 4)
void extrusion_kernel(const float* __restrict__ polygons,     // [B,N,P,2]
                      const float* __restrict__ attributes,   // [B,8]
                      const float* __restrict__ validity,     // [B,N]
                      float* __restrict__ out)                // [B,V,V,V]
{
    __shared__ float4 sA[NEDGES];   // x0, y0, ex, ey
    __shared__ float2 sB[NEDGES];   // 1/(|e|^2+eps), 1/(ey+eps)
    __shared__ int    sValid[NPOLY];

    const int b   = blockIdx.y;
    const int tid = threadIdx.x;

    // ---- cooperative precompute of per-edge invariants ----
    const float* pb = polygons + (size_t)b * NEDGES * 2;
    for (int e = tid; e < NEDGES; e += blockDim.x) {
        int n = e >> 5;
        int p = e & 31;
        int p1 = (p + 1) & 31;
        float x0 = pb[(n * PEDGE + p ) * 2 + 0];
        float y0 = pb[(n * PEDGE + p ) * 2 + 1];
        float x1 = pb[(n * PEDGE + p1) * 2 + 0];
        float y1 = pb[(n * PEDGE + p1) * 2 + 1];
        float ex = x1 - x0;
        float ey = y1 - y0;
        float inv_esq = 1.0f / (ex * ex + ey * ey + EPS);
        float inv_dy  = 1.0f / (ey + EPS);
        sA[e] = make_float4(x0, y0, ex, ey);
        sB[e] = make_float2(inv_esq, inv_dy);
    }
    if (tid < NPOLY) {
        sValid[tid] = (validity[b * NPOLY + tid] >= 0.5f) ? 1 : 0;
    }
    __syncthreads();

    // ---- this thread's grid point ----
    const int idx = blockIdx.x * blockDim.x + tid;   // 0..9215
    const int gy = idx / V;
    const int gx = idx - gy * V;
    const float inv_vm1 = 1.0f / (float)(V - 1);
    const float px = (float)gx * inv_vm1;
    const float py = (float)gy * inv_vm1;

    float combined = 0.0f;

    for (int n = 0; n < NPOLY; ++n) {
        if (!sValid[n]) continue;          // warp-uniform skip
        float min_d2 = 3.402823e38f;
        unsigned parity = 0u;
        const int base = n << 5;
        #pragma unroll 8
        for (int p = 0; p < PEDGE; ++p) {
            float4 a  = sA[base + p];
            float2 bb = sB[base + p];
            float vx = px - a.x;
            float vy = py - a.y;           // == py - y0 (reused for crossing)
            // closest-point distance^2 to segment
            float t  = __saturatef((vx * a.z + vy * a.w) * bb.x);
            float dx = vx - t * a.z;
            float dy = vy - t * a.w;
            float d2 = dx * dx + dy * dy;
            min_d2 = fminf(min_d2, d2);
            // ray-crossing parity:
            // y_crosses == (y0 <= py) XOR (y1 <= py); inter_x > px
            bool c0 = (a.y <= py);
            bool c1 = (a.y + a.w <= py);
            float ix = a.x + a.z * (vy * bb.y);
            parity ^= (unsigned)((c0 != c1) && (ix > px));
        }
        float d   = sqrtf(min_d2);
        float sdf = parity ? -d : d;
        // sigmoid(-sdf*SHARPNESS) = 1 / (1 + exp(sdf*SHARPNESS))
        float m = 1.0f / (1.0f + __expf(SHARPNESS * sdf));
        combined = fmaxf(combined, m);
    }

    // ---- fused z-extrusion ----
    float hraw = __ldg(&attributes[b * 8]);
    float hv = fminf(fmaxf(rintf(__saturatef(hraw) * (float)V), 1.0f), (float)V);
    int hvi = (int)hv;

    float* ob = out + ((size_t)b * V) * (V * V) + (size_t)gy * V + gx;
    #pragma unroll 4
    for (int z = 0; z < V; ++z) {
        ob[(size_t)z * (V * V)] = (z < hvi) ? combined : 0.0f;
    }
}

extern "C" void kernel_launch(void* const* d_in, const int* in_sizes, int n_in,
                              void* d_out, int out_size)
{
    const float* polygons   = (const float*)d_in[0];  // [4,32,32,2]
    const float* attributes = (const float*)d_in[1];  // [4,8]
    const float* validity   = (const float*)d_in[2];  // [4,32]
    float* out = (float*)d_out;                       // [4,96,96,96]

    dim3 grid(V * V / 256, 4);   // (36, 4)
    dim3 block(256);
    extrusion_kernel<<<grid, block>>>(polygons, attributes, validity, out);
}

// round 5
// speedup vs baseline: 1.1651x; 1.1651x over previous
#include <cuda_runtime.h>
#include <cuda_bf16.h>
#include <cstdint>

// DifferentiableExtrusion: B=4, N=32 polygons, P=32 edges, V=96 grid.
// out[b,z,y,x] = (z < hv[b]) * max_{n valid} sigmoid(-100 * sdf_n(x,y))
//
// R3 changes:
//  * max over sigmoids == sigmoid of min sdf  -> ONE sqrt/exp/rcp per point
//    (track max d^2 over inside polys, min d^2 over outside polys).
//  * 4 polygon-groups across threadIdx.y -> 576 CTAs, ~31 warps/SM (was 8).
//    Groups combined via tiny smem min/max reduction.
//  * z-extrusion stores split 24-per-group-thread, still fully coalesced.

#define V 96
#define NPOLY 32
#define PEDGE 32
#define NEDGES (NPOLY * PEDGE)   // 1024
#define SHARPNESS 100.0f
#define EPS 1e-8f
#define FLT_BIG 3.402823466e38f

__global__ __launch_bounds__(256, 4)
void extrusion_kernel(const float* __restrict__ polygons,     // [B,N,P,2]
                      const float* __restrict__ attributes,   // [B,8]
                      const float* __restrict__ validity,     // [B,N]
                      float* __restrict__ out)                // [B,V,V,V]
{
    __shared__ float4 sA[NEDGES];        // x0, y0, ex, ey
    __shared__ float4 sB[NEDGES];        // 1/(|e|^2+eps), 1/(ey+eps), y1, --
    __shared__ float2 sRed[2][4][32];    // (negmax_d2, posmin_d2) per (tz, group, tx)
    __shared__ int    sValid[NPOLY];

    const int b  = blockIdx.y;
    const int tx = threadIdx.x;          // 32: point-in-warp
    const int ty = threadIdx.y;          // 4 : polygon group
    const int tz = threadIdx.z;          // 2 : point tile
    const int tid = tx + 32 * (ty + 4 * tz);

    // ---- cooperative precompute of per-edge invariants ----
    const float* pb = polygons + (size_t)b * NEDGES * 2;
    for (int e = tid; e < NEDGES; e += 256) {
        int n = e >> 5;
        int p = e & 31;
        int p1 = (p + 1) & 31;
        float x0 = pb[(n * PEDGE + p ) * 2 + 0];
        float y0 = pb[(n * PEDGE + p ) * 2 + 1];
        float x1 = pb[(n * PEDGE + p1) * 2 + 0];
        float y1 = pb[(n * PEDGE + p1) * 2 + 1];
        float ex = x1 - x0;
        float ey = y1 - y0;
        sA[e] = make_float4(x0, y0, ex, ey);
        sB[e] = make_float4(1.0f / (ex * ex + ey * ey + EPS),
                            1.0f / (ey + EPS),
                            y1, 0.0f);
    }
    if (tid < NPOLY) {
        sValid[tid] = (validity[b * NPOLY + tid] >= 0.5f) ? 1 : 0;
    }
    __syncthreads();

    // ---- this thread's grid point ----
    const int pidx = blockIdx.x * 64 + tz * 32 + tx;   // 0..9215
    const int gy = pidx / V;
    const int gx = pidx - gy * V;
    const float inv_vm1 = 1.0f / (float)(V - 1);
    const float px = (float)gx * inv_vm1;
    const float py = (float)gy * inv_vm1;

    // accumulate over this thread's 8 polygons
    float negmax = -1.0f;        // max d^2 among INSIDE polygons
    float posmin = FLT_BIG;      // min d^2 among OUTSIDE polygons

    const int n0 = ty * 8;
    for (int n = n0; n < n0 + 8; ++n) {
        if (!sValid[n]) continue;          // warp-uniform skip
        float min_d2 = FLT_BIG;
        unsigned parity = 0u;
        const int base = n << 5;
        #pragma unroll 8
        for (int p = 0; p < PEDGE; ++p) {
            float4 a  = sA[base + p];
            float4 bb = sB[base + p];
            float vx = px - a.x;
            float vy = py - a.y;
            // closest-point distance^2 to segment
            float t  = __saturatef((vx * a.z + vy * a.w) * bb.x);
            float dx = vx - t * a.z;
            float dy = vy - t * a.w;
            float d2 = dx * dx + dy * dy;
            min_d2 = fminf(min_d2, d2);
            // ray-crossing parity: (y0<=py) XOR (y1<=py), and inter_x > px
            bool c0 = (a.y  <= py);
            bool c1 = (bb.z <= py);
            float ix = a.x + a.z * (vy * bb.y);
            parity ^= (unsigned)((c0 != c1) && (ix > px));
        }
        if (parity) negmax = fmaxf(negmax, min_d2);
        else        posmin = fminf(posmin, min_d2);
    }

    // ---- combine polygon groups ----
    sRed[tz][ty][tx] = make_float2(negmax, posmin);
    __syncthreads();

    float ng = -1.0f, ps = FLT_BIG;
    #pragma unroll
    for (int g = 0; g < 4; ++g) {
        float2 r = sRed[tz][g][tx];
        ng = fmaxf(ng, r.x);
        ps = fminf(ps, r.y);
    }

    // single sqrt + sigmoid per point
    bool inside = (ng >= 0.0f);
    float d   = sqrtf(inside ? ng : ps);
    float sdf = inside ? -d : d;
    // no-valid-polygon case: ps=FLT_BIG -> exp overflows to inf -> m = 0  (matches ref)
    float m = 1.0f / (1.0f + __expf(SHARPNESS * sdf));

    // ---- fused z-extrusion (24 z-slices per group-thread) ----
    float hraw = __ldg(&attributes[b * 8]);
    float hv = fminf(fmaxf(rintf(__saturatef(hraw) * (float)V), 1.0f), (float)V);
    int hvi = (int)hv;

    float* ob = out + (size_t)b * V * V * V + (size_t)gy * V + gx;
    const int z0 = ty * 24;
    #pragma unroll 4
    for (int z = z0; z < z0 + 24; ++z) {
        ob[(size_t)z * (V * V)] = (z < hvi) ? m : 0.0f;
    }
}

extern "C" void kernel_launch(void* const* d_in, const int* in_sizes, int n_in,
                              void* d_out, int out_size)
{
    const float* polygons   = (const float*)d_in[0];  // [4,32,32,2]
    const float* attributes = (const float*)d_in[1];  // [4,8]
    const float* validity   = (const float*)d_in[2];  // [4,32]
    float* out = (float*)d_out;                       // [4,96,96,96]

    dim3 grid(V * V / 64, 4);    // (144, 4) = 576 CTAs
    dim3 block(32, 4, 2);        // 256 threads
    extrusion_kernel<<<grid, block>>>(polygons, attributes, validity, out);
}

// round 6
// speedup vs baseline: 1.2872x; 1.1049x over previous
#include <cuda_runtime.h>
#include <cuda_bf16.h>
#include <cstdint>

// DifferentiableExtrusion: B=4, N=32 polygons, P=32 edges, V=96 grid.
// out[b,z,y,x] = (z < hv[b]) * max_{n valid} sigmoid(-100 * sdf_n(x,y))
//
// R5 changes:
//  * valid-polygon compaction (ballot+popc) with strided distribution across
//    the 4 polygon groups -> balanced critical path (ceil(nv/4) vs max-of-Bin(8,.5)),
//    no divergent skip branch.
//  * warp-uniform early exit: once all 32 lanes have an inside-distance^2 > 0.01
//    (d > 0.1), sigmoid is within 4.5e-5 of 1 -> remaining polygons can't matter.
//  * dual min-d2 accumulators (even/odd edges) to split the FMNMX dep chain.
//  * crossing/distance arithmetic kept bit-identical to the validated R3 form.

#define V 96
#define NPOLY 32
#define PEDGE 32
#define NEDGES (NPOLY * PEDGE)   // 1024
#define SHARPNESS 100.0f
#define EPS 1e-8f
#define FLT_BIG 3.402823466e38f
#define DEEP_IN2 0.01f           // (0.1)^2 : sigmoid(100*0.1) = 1 - 4.5e-5

__global__ __launch_bounds__(256, 4)
void extrusion_kernel(const float* __restrict__ polygons,     // [B,N,P,2]
                      const float* __restrict__ attributes,   // [B,8]
                      const float* __restrict__ validity,     // [B,N]
                      float* __restrict__ out)                // [B,V,V,V]
{
    __shared__ float4 sA[NEDGES];        // x0, y0, ex, ey
    __shared__ float4 sB[NEDGES];        // 1/(|e|^2+eps), 1/(ey+eps), y1, --
    __shared__ float2 sRed[2][4][32];    // (negmax_d2, posmin_d2) per (tz, group, tx)
    __shared__ int    sList[NPOLY];      // compacted valid polygon indices
    __shared__ int    sNv;

    const int b  = blockIdx.y;
    const int tx = threadIdx.x;          // 32: point-in-warp
    const int ty = threadIdx.y;          // 4 : polygon group
    const int tz = threadIdx.z;          // 2 : point tile
    const int tid = tx + 32 * (ty + 4 * tz);

    // ---- cooperative precompute of per-edge invariants ----
    const float* pb = polygons + (size_t)b * NEDGES * 2;
    #pragma unroll
    for (int e = tid; e < NEDGES; e += 256) {
        int n = e >> 5;
        int p = e & 31;
        int p1 = (p + 1) & 31;
        float x0 = pb[(n * PEDGE + p ) * 2 + 0];
        float y0 = pb[(n * PEDGE + p ) * 2 + 1];
        float x1 = pb[(n * PEDGE + p1) * 2 + 0];
        float y1 = pb[(n * PEDGE + p1) * 2 + 1];
        float ex = x1 - x0;
        float ey = y1 - y0;
        sA[e] = make_float4(x0, y0, ex, ey);
        sB[e] = make_float4(1.0f / (ex * ex + ey * ey + EPS),
                            1.0f / (ey + EPS),
                            y1, 0.0f);
    }
    // ---- compact valid polygon list (warp 0) ----
    if (tid < 32) {
        bool v = (validity[b * NPOLY + tid] >= 0.5f);
        unsigned m = __ballot_sync(0xffffffffu, v);
        if (v) sList[__popc(m & ((1u << tid) - 1u))] = tid;
        if (tid == 0) sNv = __popc(m);
    }
    __syncthreads();
    const int nv = sNv;

    // ---- this thread's grid point ----
    const int pidx = blockIdx.x * 64 + tz * 32 + tx;   // 0..9215
    const int gy = pidx / V;
    const int gx = pidx - gy * V;
    const float inv_vm1 = 1.0f / (float)(V - 1);
    const float px = (float)gx * inv_vm1;
    const float py = (float)gy * inv_vm1;

    float negmax = -1.0f;        // max d^2 among INSIDE polygons
    float posmin = FLT_BIG;      // min d^2 among OUTSIDE polygons

    // strided, balanced distribution of valid polygons across the 4 groups
    for (int i = ty; i < nv; i += 4) {
        const int base = sList[i] << 5;
        float mda = FLT_BIG, mdb = FLT_BIG;   // dual accumulators
        unsigned parity = 0u;
        #pragma unroll
        for (int p = 0; p < PEDGE; p += 2) {
            {   // edge p
                float4 a  = sA[base + p];
                float4 bb = sB[base + p];
                float vx = px - a.x;
                float vy = py - a.y;
                float t  = __saturatef((vx * a.z + vy * a.w) * bb.x);
                float dx = vx - t * a.z;
                float dy = vy - t * a.w;
                mda = fminf(mda, dx * dx + dy * dy);
                bool c0 = (a.y  <= py);
                bool c1 = (bb.z <= py);
                float ix = a.x + a.z * (vy * bb.y);
                parity ^= (unsigned)((c0 != c1) && (ix > px));
            }
            {   // edge p+1
                float4 a  = sA[base + p + 1];
                float4 bb = sB[base + p + 1];
                float vx = px - a.x;
                float vy = py - a.y;
                float t  = __saturatef((vx * a.z + vy * a.w) * bb.x);
                float dx = vx - t * a.z;
                float dy = vy - t * a.w;
                mdb = fminf(mdb, dx * dx + dy * dy);
                bool c0 = (a.y  <= py);
                bool c1 = (bb.z <= py);
                float ix = a.x + a.z * (vy * bb.y);
                parity ^= (unsigned)((c0 != c1) && (ix > px));
            }
        }
        float min_d2 = fminf(mda, mdb);
        if (parity & 1u) negmax = fmaxf(negmax, min_d2);
        else             posmin = fminf(posmin, min_d2);
        // warp-uniform early exit: all lanes deep inside -> m is 1 to <1e-4
        if (__all_sync(0xffffffffu, negmax > DEEP_IN2)) break;
    }

    // ---- combine polygon groups ----
    sRed[tz][ty][tx] = make_float2(negmax, posmin);
    __syncthreads();

    float ng = -1.0f, ps = FLT_BIG;
    #pragma unroll
    for (int g = 0; g < 4; ++g) {
        float2 r = sRed[tz][g][tx];
        ng = fmaxf(ng, r.x);
        ps = fminf(ps, r.y);
    }

    // single sqrt + sigmoid per point
    bool inside = (ng >= 0.0f);
    float d   = sqrtf(inside ? ng : ps);
    float sdf = inside ? -d : d;
    // no-valid-polygon case: ps=FLT_BIG -> exp -> inf -> m = 0  (matches ref)
    float m = 1.0f / (1.0f + __expf(SHARPNESS * sdf));

    // ---- fused z-extrusion (24 z-slices per group-thread, coalesced) ----
    float hraw = __ldg(&attributes[b * 8]);
    float hv = fminf(fmaxf(rintf(__saturatef(hraw) * (float)V), 1.0f), (float)V);
    int hvi = (int)hv;

    float* ob = out + (size_t)b * V * V * V + (size_t)gy * V + gx;
    const int z0 = ty * 24;
    #pragma unroll 4
    for (int z = z0; z < z0 + 24; ++z) {
        ob[(size_t)z * (V * V)] = (z < hvi) ? m : 0.0f;
    }
}

extern "C" void kernel_launch(void* const* d_in, const int* in_sizes, int n_in,
                              void* d_out, int out_size)
{
    const float* polygons   = (const float*)d_in[0];  // [4,32,32,2]
    const float* attributes = (const float*)d_in[1];  // [4,8]
    const float* validity   = (const float*)d_in[2];  // [4,32]
    float* out = (float*)d_out;                       // [4,96,96,96]

    dim3 grid(V * V / 64, 4);    // (144, 4) = 576 CTAs
    dim3 block(32, 4, 2);        // 256 threads
    extrusion_kernel<<<grid, block>>>(polygons, attributes, validity, out);
}

// round 8
// speedup vs baseline: 1.6072x; 1.2486x over previous
#include <cuda_runtime.h>
#include <cuda_bf16.h>
#include <cstdint>

// DifferentiableExtrusion: B=4, N=32 polygons, P=32 edges, V=96 grid.
// out[b,z,y,x] = (z < hv[b]) * max_{n valid} sigmoid(-100 * sdf_n(x,y))
//
// R7 changes:
//  * Warps are row-aligned (96 = 3*32) -> py, vy=py-y0, and the whole
//    y-crossing test are warp-uniform. Precompute per (row, edge):
//    vy and ix (intersection x, sentinel -1 when edge doesn't cross the row).
//    Inner loop crossing test collapses to one compare: parity += (ix > px).
//  * Inner loop: 1x LDS.128 + 1x LDS.64 + ~11 math ops per edge (was ~19).
//  * All float op orderings identical to validated kernel -> bit-identical d2
//    and parity.
//  * launch_bounds(256,5) to lift occupancy (simpler loop -> fewer regs).

#define V 96
#define NPOLY 32
#define PEDGE 32
#define NEDGES (NPOLY * PEDGE)   // 1024
#define SHARPNESS 100.0f
#define EPS 1e-8f
#define FLT_BIG 3.402823466e38f
#define DEEP_IN2 0.01f           // (0.1)^2 : sigmoid(100*0.1) = 1 - 4.5e-5

__global__ __launch_bounds__(256, 5)
void extrusion_kernel(const float* __restrict__ polygons,     // [B,N,P,2]
                      const float* __restrict__ attributes,   // [B,8]
                      const float* __restrict__ validity,     // [B,N]
                      float* __restrict__ out)                // [B,V,V,V]
{
    __shared__ float4 sE[NEDGES];        // x0, ex, ey, inv_esq
    __shared__ float2 sR[2][NEDGES];     // per row: vy, ix (or -1 sentinel)
    __shared__ float2 sRed[2][4][32];    // (negmax_d2, posmin_d2)
    __shared__ int    sList[NPOLY];
    __shared__ int    sNv;

    const int b  = blockIdx.y;
    const int tx = threadIdx.x;          // 32: point-in-warp (x)
    const int ty = threadIdx.y;          // 4 : polygon group
    const int tz = threadIdx.z;          // 2 : point tile / row id
    const int tid = tx + 32 * (ty + 4 * tz);

    const float inv_vm1 = 1.0f / (float)(V - 1);
    // row y for each tile (warp-uniform; 32-aligned chunks never straddle rows)
    const int gy0 = (blockIdx.x * 64      ) / V;
    const int gy1 = (blockIdx.x * 64 + 32 ) / V;

    // ---- build per-edge tables: sE once, sR per row ----
    const float* pb = polygons + (size_t)b * NEDGES * 2;
    #pragma unroll
    for (int e = tid; e < 2 * NEDGES; e += 256) {
        int r   = e >> 10;          // row 0/1
        int idx = e & (NEDGES - 1);
        int n = idx >> 5;
        int p = idx & 31;
        int p1 = (p + 1) & 31;
        float x0 = pb[(n * PEDGE + p ) * 2 + 0];
        float y0 = pb[(n * PEDGE + p ) * 2 + 1];
        float x1 = pb[(n * PEDGE + p1) * 2 + 0];
        float y1 = pb[(n * PEDGE + p1) * 2 + 1];
        float ex = x1 - x0;
        float ey = y1 - y0;
        float inv_esq = 1.0f / (ex * ex + ey * ey + EPS);
        float inv_dy  = 1.0f / (ey + EPS);
        float py = (float)(r ? gy1 : gy0) * inv_vm1;
        float vy = py - y0;
        bool  yc = (y0 <= py) != (y1 <= py);
        float ix = yc ? (x0 + ex * (vy * inv_dy)) : -1.0f;
        if (r == 0) sE[idx] = make_float4(x0, ex, ey, inv_esq);
        sR[r][idx] = make_float2(vy, ix);
    }
    if (tid < 32) {
        bool v = (validity[b * NPOLY + tid] >= 0.5f);
        unsigned m = __ballot_sync(0xffffffffu, v);
        if (v) sList[__popc(m & ((1u << tid) - 1u))] = tid;
        if (tid == 0) sNv = __popc(m);
    }
    __syncthreads();
    const int nv = sNv;

    // ---- this thread's grid point ----
    const int pidx = blockIdx.x * 64 + tz * 32 + tx;
    const int gy = tz ? gy1 : gy0;
    const int gx = pidx - gy * V;
    const float px = (float)gx * inv_vm1;

    float negmax = -1.0f;        // max d^2 among INSIDE polygons
    float posmin = FLT_BIG;      // min d^2 among OUTSIDE polygons

    const float2* __restrict__ rowR = sR[tz];

    for (int i = ty; i < nv; i += 4) {
        const int base = sList[i] << 5;
        float mda = FLT_BIG, mdb = FLT_BIG;
        int cnt = 0;
        #pragma unroll
        for (int p = 0; p < PEDGE; p += 2) {
            {
                float4 a  = sE[base + p];          // x0, ex, ey, inv_esq
                float2 rr = rowR[base + p];        // vy, ix
                float vx = px - a.x;
                float t  = __saturatef(fmaf(rr.x, a.z, vx * a.y) * a.w);
                float dx = fmaf(-t, a.y, vx);
                float dy = fmaf(-t, a.z, rr.x);
                mda = fminf(mda, fmaf(dy, dy, dx * dx));
                cnt += (rr.y > px);
            }
            {
                float4 a  = sE[base + p + 1];
                float2 rr = rowR[base + p + 1];
                float vx = px - a.x;
                float t  = __saturatef(fmaf(rr.x, a.z, vx * a.y) * a.w);
                float dx = fmaf(-t, a.y, vx);
                float dy = fmaf(-t, a.z, rr.x);
                mdb = fminf(mdb, fmaf(dy, dy, dx * dx));
                cnt += (rr.y > px);
            }
        }
        float min_d2 = fminf(mda, mdb);
        if (cnt & 1) negmax = fmaxf(negmax, min_d2);
        else         posmin = fminf(posmin, min_d2);
        // warp-uniform early exit: all lanes deep inside -> m within 1e-4 of 1
        if (__all_sync(0xffffffffu, negmax > DEEP_IN2)) break;
    }

    // ---- combine polygon groups ----
    sRed[tz][ty][tx] = make_float2(negmax, posmin);
    __syncthreads();

    float ng = -1.0f, ps = FLT_BIG;
    #pragma unroll
    for (int g = 0; g < 4; ++g) {
        float2 r = sRed[tz][g][tx];
        ng = fmaxf(ng, r.x);
        ps = fminf(ps, r.y);
    }

    bool inside = (ng >= 0.0f);
    float d   = sqrtf(inside ? ng : ps);
    float sdf = inside ? -d : d;
    // no-valid-polygon: ps=FLT_BIG -> exp -> inf -> m = 0 (matches ref)
    float m = 1.0f / (1.0f + __expf(SHARPNESS * sdf));

    // ---- fused z-extrusion (24 z-slices per group-thread, coalesced) ----
    float hraw = __ldg(&attributes[b * 8]);
    float hv = fminf(fmaxf(rintf(__saturatef(hraw) * (float)V), 1.0f), (float)V);
    int hvi = (int)hv;

    float* ob = out + (size_t)b * V * V * V + (size_t)gy * V + gx;
    const int z0 = ty * 24;
    #pragma unroll 4
    for (int z = z0; z < z0 + 24; ++z) {
        ob[(size_t)z * (V * V)] = (z < hvi) ? m : 0.0f;
    }
}

extern "C" void kernel_launch(void* const* d_in, const int* in_sizes, int n_in,
                              void* d_out, int out_size)
{
    const float* polygons   = (const float*)d_in[0];  // [4,32,32,2]
    const float* attributes = (const float*)d_in[1];  // [4,8]
    const float* validity   = (const float*)d_in[2];  // [4,32]
    float* out = (float*)d_out;                       // [4,96,96,96]

    dim3 grid(V * V / 64, 4);    // (144, 4) = 576 CTAs
    dim3 block(32, 4, 2);        // 256 threads
    extrusion_kernel<<<grid, block>>>(polygons, attributes, validity, out);
}